// round 5
// baseline (speedup 1.0000x reference)
#include <cuda_runtime.h>
#include <math.h>

// CausalGRNEMA exact chunked scan, warp-autonomous:
//  pass1: per-(b,chunk) warp scans LC timesteps from state 0 -> aggregate S (f-units)
//  pass2: serial combine over chunks -> exact carry-in per chunk (+ builds g_tab)
//  pass3: per-(b,chunk) warp rescans with carry-in; channel mean warp-internal.
//         R5: 2-timestep interleaving -> 2-deep prefetch (8 LDG in flight) and
//         two overlapped shfl reduction chains per iteration.
// State scaled: f = ema/OMA, f' = alpha*f + x^2.

#define ALPHA   0.99f
#define OMA     0.01f
#define EPSF    1e-6f
#define EMAINIT 1e-4f

static constexpr int B  = 16;
static constexpr int T  = 8192;
static constexpr int C  = 512;
static constexpr int C4 = C / 4;          // 128 float4 columns
static constexpr int LC = 64;             // timesteps per warp task
static constexpr int NCH = T / LC;        // 128 chunks
static constexpr int WPB = 8;             // warps per block
static constexpr int NTASK = B * NCH;     // 2048 warp tasks

__device__ float2 g_tab[T];               // (EPS*D_t, EPS*sqrt(D_t)), D_t = 1-alpha^(t+1)+EPS
__device__ float  g_S[NTASK * C];         // chunk aggregates (f-units)
__device__ float  g_Ein[NTASK * C];       // exact carry-in per chunk (f-units)

// ---- pass1: warp-autonomous local scan, aggregate only ----
__global__ __launch_bounds__(256, 3)
void pass1_kernel(const float* __restrict__ x) {
    const int warp = threadIdx.x >> 5;
    const int lane = threadIdx.x & 31;
    const int task = blockIdx.x * WPB + warp;
    const int b = task >> 7;
    const int k = task & (NCH - 1);

    const float4* __restrict__ xb =
        (const float4*)x + ((size_t)b * T + (size_t)k * LC) * C4 + lane;

    float4 f[4], cur[4], nxt[4];
    #pragma unroll
    for (int j = 0; j < 4; j++) f[j] = make_float4(0.f, 0.f, 0.f, 0.f);
    #pragma unroll
    for (int j = 0; j < 4; j++) cur[j] = xb[j * 32];

    for (int t = 0; t < LC; t++) {
        if (t + 1 < LC) {
            #pragma unroll
            for (int j = 0; j < 4; j++) nxt[j] = xb[(size_t)(t + 1) * C4 + j * 32];
        }
        #pragma unroll
        for (int j = 0; j < 4; j++) {
            f[j].x = fmaf(ALPHA, f[j].x, cur[j].x * cur[j].x);
            f[j].y = fmaf(ALPHA, f[j].y, cur[j].y * cur[j].y);
            f[j].z = fmaf(ALPHA, f[j].z, cur[j].z * cur[j].z);
            f[j].w = fmaf(ALPHA, f[j].w, cur[j].w * cur[j].w);
        }
        #pragma unroll
        for (int j = 0; j < 4; j++) cur[j] = nxt[j];
    }
    float4* __restrict__ S4 = (float4*)g_S + (size_t)task * C4 + lane;
    #pragma unroll
    for (int j = 0; j < 4; j++) S4[j * 32] = f[j];
}

// ---- pass2: build g_tab + exact carry combine across chunks ----
__global__ void pass2_kernel() {
    const int idx = blockIdx.x * blockDim.x + threadIdx.x;  // 0..B*C-1 (== T)
    if (idx < T) {
        double D = 1.0 - exp((double)(idx + 1) * log(0.99)) + 1e-6;
        g_tab[idx] = make_float2((float)(1e-6 * D), (float)(1e-6 * sqrt(D)));
    }
    if (idx >= B * C) return;
    const int b = idx / C;
    const int c = idx % C;
    const float aL = (float)exp((double)LC * log(0.99));
    float E = EMAINIT / OMA;              // f-units
    #pragma unroll 8
    for (int k = 0; k < NCH; k++) {
        const size_t o = ((size_t)b * NCH + k) * C + c;
        g_Ein[o] = E;
        E = fmaf(aL, E, g_S[o]);
    }
}

// ---- pass3: warp-autonomous rescan, 2-timestep interleave ----
__global__ __launch_bounds__(256, 2)
void pass3_kernel(const float* __restrict__ x,
                  const float* __restrict__ gamma,
                  const float* __restrict__ beta,
                  float* __restrict__ y) {
    __shared__ float4 sg[C4], sb[C4];
    {
        const int tid = threadIdx.x;
        if (tid < C4)       sg[tid]      = ((const float4*)gamma)[tid];
        else                sb[tid - C4] = ((const float4*)beta)[tid - C4];
    }
    __syncthreads();   // once

    const int warp = threadIdx.x >> 5;
    const int lane = threadIdx.x & 31;
    const int task = blockIdx.x * WPB + warp;
    const int b = task >> 7;
    const int k = task & (NCH - 1);
    const int tbase = k * LC;

    const float4* __restrict__ xb =
        (const float4*)x + ((size_t)b * T + tbase) * C4 + lane;
    float4* __restrict__ yb =
        (float4*)y + ((size_t)b * T + tbase) * C4 + lane;

    float4 f[4];
    {
        const float4* __restrict__ E4 = (const float4*)g_Ein + (size_t)task * C4 + lane;
        #pragma unroll
        for (int j = 0; j < 4; j++) f[j] = E4[j * 32];
    }

    float4 cur[2][4], nxt[2][4];
    #pragma unroll
    for (int j = 0; j < 4; j++) cur[0][j] = xb[j * 32];
    #pragma unroll
    for (int j = 0; j < 4; j++) cur[1][j] = xb[C4 + j * 32];

    for (int t = 0; t < LC; t += 2) {
        // prefetch next pair (2-deep: in flight across the full pair of timesteps)
        if (t + 2 < LC) {
            #pragma unroll
            for (int j = 0; j < 4; j++) nxt[0][j] = xb[(size_t)(t + 2) * C4 + j * 32];
            #pragma unroll
            for (int j = 0; j < 4; j++) nxt[1][j] = xb[(size_t)(t + 3) * C4 + j * 32];
        }
        const float2 cs0 = g_tab[tbase + t];
        const float2 cs1 = g_tab[tbase + t + 1];

        // scan timestep t
        float4 s0[4];
        float acc0 = 0.0f;
        #pragma unroll
        for (int j = 0; j < 4; j++) {
            f[j].x = fmaf(ALPHA, f[j].x, cur[0][j].x * cur[0][j].x);
            f[j].y = fmaf(ALPHA, f[j].y, cur[0][j].y * cur[0][j].y);
            f[j].z = fmaf(ALPHA, f[j].z, cur[0][j].z * cur[0][j].z);
            f[j].w = fmaf(ALPHA, f[j].w, cur[0][j].w * cur[0][j].w);
            float vx = fmaf(OMA, f[j].x, cs0.x);
            float vy = fmaf(OMA, f[j].y, cs0.x);
            float vz = fmaf(OMA, f[j].z, cs0.x);
            float vw = fmaf(OMA, f[j].w, cs0.x);
            s0[j].x = __frsqrt_rn(vx) * vx;
            s0[j].y = __frsqrt_rn(vy) * vy;
            s0[j].z = __frsqrt_rn(vz) * vz;
            s0[j].w = __frsqrt_rn(vw) * vw;
            acc0 += (s0[j].x + s0[j].y) + (s0[j].z + s0[j].w);
        }
        // scan timestep t+1 (independent of acc0's shfl chain)
        float4 s1[4];
        float acc1 = 0.0f;
        #pragma unroll
        for (int j = 0; j < 4; j++) {
            f[j].x = fmaf(ALPHA, f[j].x, cur[1][j].x * cur[1][j].x);
            f[j].y = fmaf(ALPHA, f[j].y, cur[1][j].y * cur[1][j].y);
            f[j].z = fmaf(ALPHA, f[j].z, cur[1][j].z * cur[1][j].z);
            f[j].w = fmaf(ALPHA, f[j].w, cur[1][j].w * cur[1][j].w);
            float vx = fmaf(OMA, f[j].x, cs1.x);
            float vy = fmaf(OMA, f[j].y, cs1.x);
            float vz = fmaf(OMA, f[j].z, cs1.x);
            float vw = fmaf(OMA, f[j].w, cs1.x);
            s1[j].x = __frsqrt_rn(vx) * vx;
            s1[j].y = __frsqrt_rn(vy) * vy;
            s1[j].z = __frsqrt_rn(vz) * vz;
            s1[j].w = __frsqrt_rn(vw) * vw;
            acc1 += (s1[j].x + s1[j].y) + (s1[j].z + s1[j].w);
        }

        // two independent butterfly reductions — interleaved by the scheduler
        #pragma unroll
        for (int d = 16; d >= 1; d >>= 1) acc0 += __shfl_xor_sync(0xffffffffu, acc0, d);
        #pragma unroll
        for (int d = 16; d >= 1; d >>= 1) acc1 += __shfl_xor_sync(0xffffffffu, acc1, d);

        const float inv0 = __fdividef(1.0f, fmaf(acc0, 1.0f / C, cs0.y));
        #pragma unroll
        for (int j = 0; j < 4; j++) {
            const float4 g4 = sg[lane + j * 32];
            const float4 b4 = sb[lane + j * 32];
            float4 o;
            o.x = fmaf(cur[0][j].x, fmaf(g4.x, s0[j].x * inv0, 1.0f), b4.x);
            o.y = fmaf(cur[0][j].y, fmaf(g4.y, s0[j].y * inv0, 1.0f), b4.y);
            o.z = fmaf(cur[0][j].z, fmaf(g4.z, s0[j].z * inv0, 1.0f), b4.z);
            o.w = fmaf(cur[0][j].w, fmaf(g4.w, s0[j].w * inv0, 1.0f), b4.w);
            yb[(size_t)t * C4 + j * 32] = o;
        }
        const float inv1 = __fdividef(1.0f, fmaf(acc1, 1.0f / C, cs1.y));
        #pragma unroll
        for (int j = 0; j < 4; j++) {
            const float4 g4 = sg[lane + j * 32];
            const float4 b4 = sb[lane + j * 32];
            float4 o;
            o.x = fmaf(cur[1][j].x, fmaf(g4.x, s1[j].x * inv1, 1.0f), b4.x);
            o.y = fmaf(cur[1][j].y, fmaf(g4.y, s1[j].y * inv1, 1.0f), b4.y);
            o.z = fmaf(cur[1][j].z, fmaf(g4.z, s1[j].z * inv1, 1.0f), b4.z);
            o.w = fmaf(cur[1][j].w, fmaf(g4.w, s1[j].w * inv1, 1.0f), b4.w);
            yb[(size_t)(t + 1) * C4 + j * 32] = o;
        }

        #pragma unroll
        for (int j = 0; j < 4; j++) cur[0][j] = nxt[0][j];
        #pragma unroll
        for (int j = 0; j < 4; j++) cur[1][j] = nxt[1][j];
    }
}

extern "C" void kernel_launch(void* const* d_in, const int* in_sizes, int n_in,
                              void* d_out, int out_size) {
    const float* x     = (const float*)d_in[0];
    const float* gamma = (const float*)d_in[1];
    const float* beta  = (const float*)d_in[2];
    float* y           = (float*)d_out;

    pass1_kernel<<<NTASK / WPB, 256>>>(x);
    pass2_kernel<<<(B * C + 255) / 256, 256>>>();
    pass3_kernel<<<NTASK / WPB, 256>>>(x, gamma, beta, y);
}